// round 3
// baseline (speedup 1.0000x reference)
#include <cuda_runtime.h>

#define NN 100000
#define EE 1600000
#define BB 64
#define HH 128
#define LN_EPS 1e-5f

// ---------------- scratch (no allocations allowed) ----------------
__device__ float d_bufA[(size_t)NN * HH];
__device__ float d_bufB[(size_t)NN * HH];
__device__ float d_agg [(size_t)NN * HH];
__device__ float d_inv [NN];
__device__ int   d_deg [NN];
__device__ float d_gsum[BB * HH];
__device__ int   d_gcnt[BB];

// ---------------- init: zero deg / pooling accumulators / out max region ----
__global__ void k_init(float* __restrict__ out_graph) {
    int i = blockIdx.x * blockDim.x + threadIdx.x;
    if (i < NN) d_deg[i] = 0;
    if (i < BB * HH) {
        d_gsum[i] = 0.f;
        int b = i >> 7, j = i & 127;
        out_graph[b * (2 * HH) + HH + j] = 0.f;  // max accumulates here (relu => >=0)
    }
    if (i < BB) d_gcnt[i] = 0;
}

// ---------------- degree + inverse degree ----------------
__global__ void k_deg(const int* __restrict__ ei) {
    int e = blockIdx.x * blockDim.x + threadIdx.x;
    if (e < EE) atomicAdd(&d_deg[ei[EE + e]], 1);
}

__global__ void k_inv() {
    int i = blockIdx.x * blockDim.x + threadIdx.x;
    if (i < NN) d_inv[i] = 1.f / (float)max(d_deg[i], 1);
}

// ---------------- zero agg buffer ----------------
__global__ void k_zero_agg() {
    int i = blockIdx.x * blockDim.x + threadIdx.x;
    if (i < NN * HH / 4) ((float4*)d_agg)[i] = make_float4(0.f, 0.f, 0.f, 0.f);
}

// ---------------- node embedder: x(9) @ W0^T + b0 -> LN -> ReLU ----------------
__global__ __launch_bounds__(128) void k_embed(
    const float* __restrict__ x, const float* __restrict__ W0,
    const float* __restrict__ b0, const float* __restrict__ g0,
    const float* __restrict__ be0)
{
    __shared__ float sW[HH * 9];
    __shared__ float sx[8][9];
    __shared__ float red0[4], red1[4];
    int tid = threadIdx.x;
#pragma unroll
    for (int k = 0; k < 9; ++k) sW[tid * 9 + k] = W0[tid * 9 + k];
    int node0 = blockIdx.x * 8;
    if (tid < 72) {
        int r = tid / 9, c = tid % 9;
        int gn = node0 + r;
        sx[r][c] = (gn < NN) ? x[(size_t)gn * 9 + c] : 0.f;
    }
    __syncthreads();
    float gv = g0[tid], bev = be0[tid], bias = b0[tid];
    for (int r = 0; r < 8; ++r) {
        int gn = node0 + r;
        if (gn >= NN) break;  // uniform across block
        float v = bias;
#pragma unroll
        for (int k = 0; k < 9; ++k) v = fmaf(sx[r][k], sW[tid * 9 + k], v);
        float s = v, s2 = v * v;
#pragma unroll
        for (int off = 16; off; off >>= 1) {
            s  += __shfl_xor_sync(0xffffffffu, s, off);
            s2 += __shfl_xor_sync(0xffffffffu, s2, off);
        }
        int w = tid >> 5;
        if ((tid & 31) == 0) { red0[w] = s; red1[w] = s2; }
        __syncthreads();
        s  = red0[0] + red0[1] + red0[2] + red0[3];
        s2 = red1[0] + red1[1] + red1[2] + red1[3];
        __syncthreads();
        float m   = s * (1.f / HH);
        float var = s2 * (1.f / HH) - m * m;
        float rs  = rsqrtf(var + LN_EPS);
        d_bufA[(size_t)gn * HH + tid] = fmaxf((v - m) * rs * gv + bev, 0.f);
    }
}

// ---------------- edge scatter: agg[dst] += h[src] (warp per edge) ----------------
__global__ __launch_bounds__(256) void k_scatter(
    const float* __restrict__ h, const int* __restrict__ ei)
{
    int gw = (blockIdx.x * 256 + threadIdx.x) >> 5;
    int lane = threadIdx.x & 31;
    if (gw >= EE) return;
    int src = ei[gw];
    int dst = ei[EE + gw];
    float4 v = *(const float4*)(h + (size_t)src * HH + lane * 4);
    float* a = d_agg + (size_t)dst * HH + lane * 4;
    atomicAdd(a + 0, v.x);
    atomicAdd(a + 1, v.y);
    atomicAdd(a + 2, v.z);
    atomicAdd(a + 3, v.w);
}

// ---------------- fused dual-GEMM + bias + LayerNorm + ReLU ----------------
// out[i,:] = relu(LN( (agg[i]*inv[i]) @ Wl^T + bl + h[i] @ Wr^T ))
// BM=64, BN=128 (full row), BK=32; 256 threads; thread tile 8 rows x 4 cols.
__global__ __launch_bounds__(256) void k_gemm(
    const float* __restrict__ h,
    const float* __restrict__ Wl, const float* __restrict__ bl,
    const float* __restrict__ Wr,
    const float* __restrict__ gamma, const float* __restrict__ beta,
    float* __restrict__ out)
{
    __shared__ float As[64][33];
    __shared__ float Bs[32][132];
    __shared__ float Cs[64][132];
    int tid  = threadIdx.x;
    int trow = tid >> 5;   // warp id 0..7 -> 8-row group
    int tcol = tid & 31;   // lane -> 4-col group
    int row0 = blockIdx.x * 64;
    float acc[8][4];
#pragma unroll
    for (int r = 0; r < 8; ++r) { acc[r][0] = acc[r][1] = acc[r][2] = acc[r][3] = 0.f; }

#pragma unroll
    for (int mat = 0; mat < 2; ++mat) {
        const float* A = mat ? h  : d_agg;
        const float* W = mat ? Wr : Wl;
        for (int k0 = 0; k0 < HH; k0 += 32) {
            // A tile: 64x32 floats = 512 float4, 2 per thread
#pragma unroll
            for (int i = 0; i < 2; ++i) {
                int idx = tid + i * 256;
                int r = idx >> 3, c = idx & 7;
                int gr = row0 + r;
                float4 v = make_float4(0.f, 0.f, 0.f, 0.f);
                if (gr < NN) {
                    v = *(const float4*)(A + (size_t)gr * HH + k0 + c * 4);
                    if (mat == 0) {
                        float s = d_inv[gr];
                        v.x *= s; v.y *= s; v.z *= s; v.w *= s;
                    }
                }
                As[r][c * 4 + 0] = v.x; As[r][c * 4 + 1] = v.y;
                As[r][c * 4 + 2] = v.z; As[r][c * 4 + 3] = v.w;
            }
            // B tile (transposed into Bs[k][j]): 128x32 floats = 1024 float4, 4/thread
#pragma unroll
            for (int i = 0; i < 4; ++i) {
                int idx = tid + i * 256;
                int j = idx >> 3, c = idx & 7;
                float4 v = *(const float4*)(W + (size_t)j * HH + k0 + c * 4);
                Bs[c * 4 + 0][j] = v.x; Bs[c * 4 + 1][j] = v.y;
                Bs[c * 4 + 2][j] = v.z; Bs[c * 4 + 3][j] = v.w;
            }
            __syncthreads();
#pragma unroll
            for (int k = 0; k < 32; ++k) {
                float4 b = *(const float4*)&Bs[k][tcol * 4];  // LDS.128, conflict-free
#pragma unroll
                for (int r = 0; r < 8; ++r) {
                    float a = As[trow * 8 + r][k];            // broadcast
                    acc[r][0] = fmaf(a, b.x, acc[r][0]);
                    acc[r][1] = fmaf(a, b.y, acc[r][1]);
                    acc[r][2] = fmaf(a, b.z, acc[r][2]);
                    acc[r][3] = fmaf(a, b.w, acc[r][3]);
                }
            }
            __syncthreads();
        }
    }

    // bias, stage full rows to shared
    float4 blv = *(const float4*)(bl + tcol * 4);
#pragma unroll
    for (int r = 0; r < 8; ++r) {
        float4 o = make_float4(acc[r][0] + blv.x, acc[r][1] + blv.y,
                               acc[r][2] + blv.z, acc[r][3] + blv.w);
        *(float4*)&Cs[trow * 8 + r][tcol * 4] = o;
    }
    __syncthreads();

    // LN + ReLU: warp `trow` normalizes its own 8 rows
    float4 gv  = *(const float4*)(gamma + tcol * 4);
    float4 bev = *(const float4*)(beta  + tcol * 4);
#pragma unroll
    for (int rr = 0; rr < 8; ++rr) {
        int r  = trow * 8 + rr;
        int gr = row0 + r;
        float4 v = *(const float4*)&Cs[r][tcol * 4];
        float s  = v.x + v.y + v.z + v.w;
        float s2 = v.x * v.x + v.y * v.y + v.z * v.z + v.w * v.w;
#pragma unroll
        for (int off = 16; off; off >>= 1) {
            s  += __shfl_xor_sync(0xffffffffu, s, off);
            s2 += __shfl_xor_sync(0xffffffffu, s2, off);
        }
        float m   = s * (1.f / HH);
        float var = s2 * (1.f / HH) - m * m;
        float rs  = rsqrtf(var + LN_EPS);
        float4 o;
        o.x = fmaxf((v.x - m) * rs * gv.x + bev.x, 0.f);
        o.y = fmaxf((v.y - m) * rs * gv.y + bev.y, 0.f);
        o.z = fmaxf((v.z - m) * rs * gv.z + bev.z, 0.f);
        o.w = fmaxf((v.w - m) * rs * gv.w + bev.w, 0.f);
        if (gr < NN) *(float4*)(out + (size_t)gr * HH + tcol * 4) = o;
    }
}

// ---------------- pooling: warp per node; sum + count + in-place int max ----------
__global__ __launch_bounds__(256) void k_pool(
    const float* __restrict__ ne, const int* __restrict__ batch,
    float* __restrict__ out_graph)
{
    int gw = (blockIdx.x * 256 + threadIdx.x) >> 5;
    int lane = threadIdx.x & 31;
    if (gw >= NN) return;
    int b = batch[gw];
    float4 v = *(const float4*)(ne + (size_t)gw * HH + lane * 4);
    float* s = d_gsum + b * HH + lane * 4;
    atomicAdd(s + 0, v.x); atomicAdd(s + 1, v.y);
    atomicAdd(s + 2, v.z); atomicAdd(s + 3, v.w);
    int* mx = (int*)(out_graph + b * (2 * HH) + HH + lane * 4);
    atomicMax(mx + 0, __float_as_int(v.x));   // values are relu'd (>=0): int order == float order
    atomicMax(mx + 1, __float_as_int(v.y));
    atomicMax(mx + 2, __float_as_int(v.z));
    atomicMax(mx + 3, __float_as_int(v.w));
    if (lane == 0) atomicAdd(&d_gcnt[b], 1);
}

__global__ void k_fin(float* __restrict__ out_graph) {
    int i = blockIdx.x * blockDim.x + threadIdx.x;
    if (i >= BB * HH) return;
    int b = i >> 7, j = i & 127;
    float c = (float)max(d_gcnt[b], 1);
    out_graph[b * (2 * HH) + j] = d_gsum[i] / c;
}

// ---------------- launch ----------------
extern "C" void kernel_launch(void* const* d_in, const int* in_sizes, int n_in,
                              void* d_out, int out_size)
{
    const float* x     = (const float*)d_in[0];
    const int*   ei    = (const int*)  d_in[1];
    const int*   batch = (const int*)  d_in[2];
    const float* W0  = (const float*)d_in[3];
    const float* b0  = (const float*)d_in[4];
    const float* g0  = (const float*)d_in[5];
    const float* be0 = (const float*)d_in[6];
    const float* Wl[3] = { (const float*)d_in[7],  (const float*)d_in[12], (const float*)d_in[17] };
    const float* bl[3] = { (const float*)d_in[8],  (const float*)d_in[13], (const float*)d_in[18] };
    const float* Wr[3] = { (const float*)d_in[9],  (const float*)d_in[14], (const float*)d_in[19] };
    const float* gg[3] = { (const float*)d_in[10], (const float*)d_in[15], (const float*)d_in[20] };
    const float* bb[3] = { (const float*)d_in[11], (const float*)d_in[16], (const float*)d_in[21] };

    float* out       = (float*)d_out;
    float* out_graph = out + (size_t)NN * HH;

    void *pA = nullptr, *pB = nullptr;
    cudaGetSymbolAddress(&pA, d_bufA);
    cudaGetSymbolAddress(&pB, d_bufB);
    float* bufA = (float*)pA;
    float* bufB = (float*)pB;

    k_init<<<(NN + 255) / 256, 256>>>(out_graph);
    k_deg <<<(EE + 255) / 256, 256>>>(ei);
    k_inv <<<(NN + 255) / 256, 256>>>();
    k_embed<<<NN / 8, 128>>>(x, W0, b0, g0, be0);

    const float* hin = bufA;
    for (int l = 0; l < 3; ++l) {
        k_zero_agg<<<(NN * HH / 4 + 255) / 256, 256>>>();
        k_scatter<<<EE / 8, 256>>>(hin, ei);
        float* ho = (l == 2) ? out : ((l == 0) ? bufB : bufA);
        k_gemm<<<(NN + 63) / 64, 256>>>(hin, Wl[l], bl[l], Wr[l], gg[l], bb[l], ho);
        hin = ho;
    }

    k_pool<<<NN / 8, 256>>>(out, batch, out_graph);
    k_fin <<<(BB * HH + 255) / 256, 256>>>(out_graph);
}

// round 4
// speedup vs baseline: 1.6989x; 1.6989x over previous
#include <cuda_runtime.h>

#define NN 100000
#define EE 1600000
#define BB 64
#define HH 128
#define LN_EPS 1e-5f

// ---------------- scratch (no allocations allowed) ----------------
__device__ float d_bufA[(size_t)NN * HH];
__device__ float d_bufB[(size_t)NN * HH];
__device__ float d_agg [(size_t)NN * HH];
__device__ float d_inv [NN];
__device__ int   d_deg [NN];
__device__ int   d_rowptr[NN + 1];
__device__ int   d_fill  [NN];
__device__ int   d_csrc  [EE];
__device__ float d_gsum[BB * HH];
__device__ int   d_gcnt[BB];

// ---------------- init ----------------
__global__ void k_init(float* __restrict__ out_graph) {
    int i = blockIdx.x * blockDim.x + threadIdx.x;
    if (i < NN) d_deg[i] = 0;
    if (i < BB * HH) {
        d_gsum[i] = 0.f;
        int b = i >> 7, j = i & 127;
        out_graph[b * (2 * HH) + HH + j] = 0.f;  // max accumulates here (relu => >=0)
    }
    if (i < BB) d_gcnt[i] = 0;
}

// ---------------- degree + inverse ----------------
__global__ void k_deg(const int* __restrict__ ei) {
    int e = blockIdx.x * blockDim.x + threadIdx.x;
    if (e < EE) atomicAdd(&d_deg[ei[EE + e]], 1);
}

__global__ void k_inv() {
    int i = blockIdx.x * blockDim.x + threadIdx.x;
    if (i < NN) d_inv[i] = 1.f / (float)max(d_deg[i], 1);
}

// ---------------- single-block prefix scan over degrees -> rowptr/fill ------
__global__ void k_scan() {
    __shared__ int ssum[1024];
    int t = threadIdx.x;
    const int CH = (NN + 1023) / 1024;       // 98
    int lo = t * CH;
    int hi = min(lo + CH, NN);
    int s = 0;
    for (int i = lo; i < hi; ++i) s += d_deg[i];
    ssum[t] = s;
    __syncthreads();
    for (int off = 1; off < 1024; off <<= 1) {
        int v = (t >= off) ? ssum[t - off] : 0;
        __syncthreads();
        ssum[t] += v;
        __syncthreads();
    }
    int excl = (t == 0) ? 0 : ssum[t - 1];
    for (int i = lo; i < hi; ++i) {
        d_rowptr[i] = excl;
        d_fill[i]   = excl;
        excl += d_deg[i];
    }
    if (t == 1023) d_rowptr[NN] = ssum[1023];
}

// ---------------- CSR fill: bucket src by dst ----------------
__global__ void k_csr(const int* __restrict__ ei) {
    int e = blockIdx.x * blockDim.x + threadIdx.x;
    if (e < EE) {
        int dst = ei[EE + e];
        int pos = atomicAdd(&d_fill[dst], 1);
        d_csrc[pos] = ei[e];
    }
}

// ---------------- node embedder: x(9) @ W0^T + b0 -> LN -> ReLU -------------
__global__ __launch_bounds__(128) void k_embed(
    const float* __restrict__ x, const float* __restrict__ W0,
    const float* __restrict__ b0, const float* __restrict__ g0,
    const float* __restrict__ be0)
{
    __shared__ float sW[HH * 9];
    __shared__ float sx[8][9];
    __shared__ float red0[4], red1[4];
    int tid = threadIdx.x;
#pragma unroll
    for (int k = 0; k < 9; ++k) sW[tid * 9 + k] = W0[tid * 9 + k];
    int node0 = blockIdx.x * 8;
    if (tid < 72) {
        int r = tid / 9, c = tid % 9;
        int gn = node0 + r;
        sx[r][c] = (gn < NN) ? x[(size_t)gn * 9 + c] : 0.f;
    }
    __syncthreads();
    float gv = g0[tid], bev = be0[tid], bias = b0[tid];
    for (int r = 0; r < 8; ++r) {
        int gn = node0 + r;
        if (gn >= NN) break;
        float v = bias;
#pragma unroll
        for (int k = 0; k < 9; ++k) v = fmaf(sx[r][k], sW[tid * 9 + k], v);
        float s = v, s2 = v * v;
#pragma unroll
        for (int off = 16; off; off >>= 1) {
            s  += __shfl_xor_sync(0xffffffffu, s, off);
            s2 += __shfl_xor_sync(0xffffffffu, s2, off);
        }
        int w = tid >> 5;
        if ((tid & 31) == 0) { red0[w] = s; red1[w] = s2; }
        __syncthreads();
        s  = red0[0] + red0[1] + red0[2] + red0[3];
        s2 = red1[0] + red1[1] + red1[2] + red1[3];
        __syncthreads();
        float m   = s * (1.f / HH);
        float var = s2 * (1.f / HH) - m * m;
        float rs  = rsqrtf(var + LN_EPS);
        d_bufA[(size_t)gn * HH + tid] = fmaxf((v - m) * rs * gv + bev, 0.f);
    }
}

// ---------------- gather aggregation: agg[i] = inv[i] * sum_j h[csr[j]] ------
// warp per node, 4-deep unroll for MLP, register accumulate, streaming store.
__global__ __launch_bounds__(256) void k_gather(const float* __restrict__ h) {
    int node = (blockIdx.x * 256 + threadIdx.x) >> 5;
    int lane = threadIdx.x & 31;
    if (node >= NN) return;
    int e   = d_rowptr[node];
    int end = d_rowptr[node + 1];
    float ax = 0.f, ay = 0.f, az = 0.f, aw = 0.f;
    for (; e + 4 <= end; e += 4) {
        int s0 = d_csrc[e], s1 = d_csrc[e + 1], s2 = d_csrc[e + 2], s3 = d_csrc[e + 3];
        float4 v0 = *(const float4*)(h + (size_t)s0 * HH + lane * 4);
        float4 v1 = *(const float4*)(h + (size_t)s1 * HH + lane * 4);
        float4 v2 = *(const float4*)(h + (size_t)s2 * HH + lane * 4);
        float4 v3 = *(const float4*)(h + (size_t)s3 * HH + lane * 4);
        ax += (v0.x + v1.x) + (v2.x + v3.x);
        ay += (v0.y + v1.y) + (v2.y + v3.y);
        az += (v0.z + v1.z) + (v2.z + v3.z);
        aw += (v0.w + v1.w) + (v2.w + v3.w);
    }
    for (; e < end; ++e) {
        int s = d_csrc[e];
        float4 v = *(const float4*)(h + (size_t)s * HH + lane * 4);
        ax += v.x; ay += v.y; az += v.z; aw += v.w;
    }
    float sc = d_inv[node];
    float4 o = make_float4(ax * sc, ay * sc, az * sc, aw * sc);
    *(float4*)(d_agg + (size_t)node * HH + lane * 4) = o;
}

// ---------------- fused dual-GEMM + bias + LayerNorm + ReLU ------------------
// out[i,:] = relu(LN( agg[i] @ Wl^T + bl + h[i] @ Wr^T ))
// BM=128, BN=128 (full row), BK=32; 256 threads; warp = 16 rows, lane = 4 cols.
__global__ __launch_bounds__(256) void k_gemm(
    const float* __restrict__ h,
    const float* __restrict__ Wl, const float* __restrict__ bl,
    const float* __restrict__ Wr,
    const float* __restrict__ gamma, const float* __restrict__ beta,
    float* __restrict__ out)
{
    __shared__ float Ast[32][132];   // transposed A tile: [k][row]
    __shared__ float Bs [32][132];   // transposed W tile: [k][outcol]
    int tid  = threadIdx.x;
    int wid  = tid >> 5;             // warp -> rows wid*16 .. +15
    int lane = tid & 31;             // lane -> cols lane*4 .. +3
    int row0 = blockIdx.x * 128;
    float acc[16][4];
#pragma unroll
    for (int r = 0; r < 16; ++r)
        acc[r][0] = acc[r][1] = acc[r][2] = acc[r][3] = 0.f;

#pragma unroll 1
    for (int mat = 0; mat < 2; ++mat) {
        const float* A = mat ? h  : d_agg;
        const float* W = mat ? Wr : Wl;
#pragma unroll 1
        for (int k0 = 0; k0 < HH; k0 += 32) {
            // A tile: 128x32 floats = 1024 float4, 4/thread, coalesced rows
#pragma unroll
            for (int i = 0; i < 4; ++i) {
                int idx = tid + i * 256;
                int r = idx >> 3, c = idx & 7;
                int gr = row0 + r;
                float4 v = make_float4(0.f, 0.f, 0.f, 0.f);
                if (gr < NN) v = *(const float4*)(A + (size_t)gr * HH + k0 + c * 4);
                Ast[c * 4 + 0][r] = v.x; Ast[c * 4 + 1][r] = v.y;
                Ast[c * 4 + 2][r] = v.z; Ast[c * 4 + 3][r] = v.w;
            }
            // B tile: 128 outcols x 32 k = 1024 float4, 4/thread
#pragma unroll
            for (int i = 0; i < 4; ++i) {
                int idx = tid + i * 256;
                int j = idx >> 3, c = idx & 7;
                float4 v = *(const float4*)(W + (size_t)j * HH + k0 + c * 4);
                Bs[c * 4 + 0][j] = v.x; Bs[c * 4 + 1][j] = v.y;
                Bs[c * 4 + 2][j] = v.z; Bs[c * 4 + 3][j] = v.w;
            }
            __syncthreads();
#pragma unroll 16
            for (int k = 0; k < 32; ++k) {
                float4 b  = *(const float4*)&Bs[k][lane * 4];       // conflict-free
                float4 a0 = *(const float4*)&Ast[k][wid * 16 + 0];  // broadcast
                float4 a1 = *(const float4*)&Ast[k][wid * 16 + 4];
                float4 a2 = *(const float4*)&Ast[k][wid * 16 + 8];
                float4 a3 = *(const float4*)&Ast[k][wid * 16 + 12];
                float a[16] = { a0.x, a0.y, a0.z, a0.w,  a1.x, a1.y, a1.z, a1.w,
                                a2.x, a2.y, a2.z, a2.w,  a3.x, a3.y, a3.z, a3.w };
#pragma unroll
                for (int r = 0; r < 16; ++r) {
                    acc[r][0] = fmaf(a[r], b.x, acc[r][0]);
                    acc[r][1] = fmaf(a[r], b.y, acc[r][1]);
                    acc[r][2] = fmaf(a[r], b.z, acc[r][2]);
                    acc[r][3] = fmaf(a[r], b.w, acc[r][3]);
                }
            }
            __syncthreads();
        }
    }

    // bias + LayerNorm + ReLU directly from registers (warp holds full rows)
    float4 blv = *(const float4*)(bl    + lane * 4);
    float4 gv  = *(const float4*)(gamma + lane * 4);
    float4 bev = *(const float4*)(beta  + lane * 4);
#pragma unroll
    for (int r = 0; r < 16; ++r) {
        int gr = row0 + wid * 16 + r;
        float4 v = make_float4(acc[r][0] + blv.x, acc[r][1] + blv.y,
                               acc[r][2] + blv.z, acc[r][3] + blv.w);
        float s  = v.x + v.y + v.z + v.w;
        float s2 = v.x * v.x + v.y * v.y + v.z * v.z + v.w * v.w;
#pragma unroll
        for (int off = 16; off; off >>= 1) {
            s  += __shfl_xor_sync(0xffffffffu, s, off);
            s2 += __shfl_xor_sync(0xffffffffu, s2, off);
        }
        float m   = s * (1.f / HH);
        float var = s2 * (1.f / HH) - m * m;
        float rs  = rsqrtf(var + LN_EPS);
        float4 o;
        o.x = fmaxf((v.x - m) * rs * gv.x + bev.x, 0.f);
        o.y = fmaxf((v.y - m) * rs * gv.y + bev.y, 0.f);
        o.z = fmaxf((v.z - m) * rs * gv.z + bev.z, 0.f);
        o.w = fmaxf((v.w - m) * rs * gv.w + bev.w, 0.f);
        if (gr < NN) *(float4*)(out + (size_t)gr * HH + lane * 4) = o;
    }
}

// ---------------- pooling ----------------
__global__ __launch_bounds__(256) void k_pool(
    const float* __restrict__ ne, const int* __restrict__ batch,
    float* __restrict__ out_graph)
{
    int gw = (blockIdx.x * 256 + threadIdx.x) >> 5;
    int lane = threadIdx.x & 31;
    if (gw >= NN) return;
    int b = batch[gw];
    float4 v = *(const float4*)(ne + (size_t)gw * HH + lane * 4);
    float* s = d_gsum + b * HH + lane * 4;
    atomicAdd(s + 0, v.x); atomicAdd(s + 1, v.y);
    atomicAdd(s + 2, v.z); atomicAdd(s + 3, v.w);
    int* mx = (int*)(out_graph + b * (2 * HH) + HH + lane * 4);
    atomicMax(mx + 0, __float_as_int(v.x));   // relu'd (>=0): int order == float order
    atomicMax(mx + 1, __float_as_int(v.y));
    atomicMax(mx + 2, __float_as_int(v.z));
    atomicMax(mx + 3, __float_as_int(v.w));
    if (lane == 0) atomicAdd(&d_gcnt[b], 1);
}

__global__ void k_fin(float* __restrict__ out_graph) {
    int i = blockIdx.x * blockDim.x + threadIdx.x;
    if (i >= BB * HH) return;
    int b = i >> 7, j = i & 127;
    float c = (float)max(d_gcnt[b], 1);
    out_graph[b * (2 * HH) + j] = d_gsum[i] / c;
}

// ---------------- launch ----------------
extern "C" void kernel_launch(void* const* d_in, const int* in_sizes, int n_in,
                              void* d_out, int out_size)
{
    const float* x     = (const float*)d_in[0];
    const int*   ei    = (const int*)  d_in[1];
    const int*   batch = (const int*)  d_in[2];
    const float* W0  = (const float*)d_in[3];
    const float* b0  = (const float*)d_in[4];
    const float* g0  = (const float*)d_in[5];
    const float* be0 = (const float*)d_in[6];
    const float* Wl[3] = { (const float*)d_in[7],  (const float*)d_in[12], (const float*)d_in[17] };
    const float* bl[3] = { (const float*)d_in[8],  (const float*)d_in[13], (const float*)d_in[18] };
    const float* Wr[3] = { (const float*)d_in[9],  (const float*)d_in[14], (const float*)d_in[19] };
    const float* gg[3] = { (const float*)d_in[10], (const float*)d_in[15], (const float*)d_in[20] };
    const float* bb[3] = { (const float*)d_in[11], (const float*)d_in[16], (const float*)d_in[21] };

    float* out       = (float*)d_out;
    float* out_graph = out + (size_t)NN * HH;

    void *pA = nullptr, *pB = nullptr;
    cudaGetSymbolAddress(&pA, d_bufA);
    cudaGetSymbolAddress(&pB, d_bufB);
    float* bufA = (float*)pA;
    float* bufB = (float*)pB;

    k_init<<<(NN + 255) / 256, 256>>>(out_graph);
    k_deg <<<(EE + 255) / 256, 256>>>(ei);
    k_inv <<<(NN + 255) / 256, 256>>>();
    k_scan<<<1, 1024>>>();
    k_csr <<<(EE + 255) / 256, 256>>>(ei);
    k_embed<<<NN / 8, 128>>>(x, W0, b0, g0, be0);

    const float* hin = bufA;
    for (int l = 0; l < 3; ++l) {
        k_gather<<<(NN + 7) / 8, 256>>>(hin);
        float* ho = (l == 2) ? out : ((l == 0) ? bufB : bufA);
        k_gemm<<<(NN + 127) / 128, 256>>>(hin, Wl[l], bl[l], Wr[l], gg[l], bb[l], ho);
        hin = ho;
    }

    k_pool<<<NN / 8, 256>>>(out, batch, out_graph);
    k_fin <<<(BB * HH + 255) / 256, 256>>>(out_graph);
}

// round 5
// speedup vs baseline: 1.9998x; 1.1772x over previous
#include <cuda_runtime.h>
#include <cstdint>

#define NN 100000
#define EE 1600000
#define BB 64
#define HH 128
#define LN_EPS 1e-5f
#define SCAN_B 391   // ceil(NN/256)

// ---------------- scratch (no allocations allowed) ----------------
__device__ float d_bufA[(size_t)NN * HH];
__device__ float d_bufB[(size_t)NN * HH];
__device__ float d_agg [(size_t)NN * HH];
__device__ float d_inv [NN];
__device__ int   d_deg [NN];
__device__ int   d_rowptr[NN + 1];
__device__ int   d_fill  [NN];
__device__ int   d_csrc  [EE];
__device__ int   d_bsum  [SCAN_B];
__device__ float d_gsum[BB * HH];
__device__ int   d_gcnt[BB];

#define PACK2(d, lo, hi) asm("mov.b64 %0, {%1, %2};" : "=l"(d) : "r"(lo), "r"(hi))
#define FMA2(d, a, b, c) asm("fma.rn.f32x2 %0, %1, %2, %3;" : "=l"(d) : "l"(a), "l"(b), "l"(c))
#define UNPK2(lo, hi, v) asm("mov.b64 {%0, %1}, %2;" : "=r"(lo), "=r"(hi) : "l"(v))

// ---------------- init ----------------
__global__ void k_init(float* __restrict__ out_graph) {
    int i = blockIdx.x * blockDim.x + threadIdx.x;
    if (i < NN) d_deg[i] = 0;
    if (i < BB * HH) {
        d_gsum[i] = 0.f;
        int b = i >> 7, j = i & 127;
        out_graph[b * (2 * HH) + HH + j] = 0.f;  // max accumulates here (relu => >=0)
    }
    if (i < BB) d_gcnt[i] = 0;
}

// ---------------- degree + inverse ----------------
__global__ void k_deg(const int* __restrict__ ei) {
    int e = blockIdx.x * blockDim.x + threadIdx.x;
    if (e < EE) atomicAdd(&d_deg[ei[EE + e]], 1);
}

__global__ void k_inv() {
    int i = blockIdx.x * blockDim.x + threadIdx.x;
    if (i < NN) d_inv[i] = 1.f / (float)max(d_deg[i], 1);
}

// ---------------- parallel 3-phase scan over degrees ----------------
__global__ __launch_bounds__(256) void k_scan1() {
    __shared__ int wsum[8];
    int t = threadIdx.x;
    int i = blockIdx.x * 256 + t;
    int v = (i < NN) ? d_deg[i] : 0;
    int s = v;
#pragma unroll
    for (int off = 16; off; off >>= 1) s += __shfl_xor_sync(0xffffffffu, s, off);
    if ((t & 31) == 0) wsum[t >> 5] = s;
    __syncthreads();
    if (t == 0) {
        int tot = 0;
#pragma unroll
        for (int w = 0; w < 8; ++w) tot += wsum[w];
        d_bsum[blockIdx.x] = tot;
    }
}

__global__ __launch_bounds__(512) void k_scan2() {
    __shared__ int sh[512];
    int t = threadIdx.x;
    int v = (t < SCAN_B) ? d_bsum[t] : 0;
    sh[t] = v;
    __syncthreads();
#pragma unroll
    for (int off = 1; off < 512; off <<= 1) {
        int u = (t >= off) ? sh[t - off] : 0;
        __syncthreads();
        sh[t] += u;
        __syncthreads();
    }
    if (t < SCAN_B) d_bsum[t] = sh[t] - v;  // exclusive
}

__global__ __launch_bounds__(256) void k_scan3() {
    __shared__ int sh[256];
    int t = threadIdx.x;
    int i = blockIdx.x * 256 + t;
    int v = (i < NN) ? d_deg[i] : 0;
    sh[t] = v;
    __syncthreads();
#pragma unroll
    for (int off = 1; off < 256; off <<= 1) {
        int u = (t >= off) ? sh[t - off] : 0;
        __syncthreads();
        sh[t] += u;
        __syncthreads();
    }
    int excl = sh[t] - v + d_bsum[blockIdx.x];
    if (i < NN) { d_rowptr[i] = excl; d_fill[i] = excl; }
    if (i == 0) d_rowptr[NN] = EE;
}

// ---------------- CSR fill: bucket src by dst ----------------
__global__ void k_csr(const int* __restrict__ ei) {
    int e = blockIdx.x * blockDim.x + threadIdx.x;
    if (e < EE) {
        int dst = ei[EE + e];
        int pos = atomicAdd(&d_fill[dst], 1);
        d_csrc[pos] = ei[e];
    }
}

// ---------------- node embedder: warp per node, no block syncs in loop ------
__global__ __launch_bounds__(256) void k_embed(
    const float* __restrict__ x, const float* __restrict__ W0,
    const float* __restrict__ b0, const float* __restrict__ g0,
    const float* __restrict__ be0)
{
    __shared__ float sW[HH * 9];
    int tid = threadIdx.x;
    int wid = tid >> 5, lane = tid & 31;
    for (int i = tid; i < HH * 9; i += 256) sW[i] = W0[i];
    __syncthreads();
    int c0 = lane * 4;
    float wreg[4][9];
#pragma unroll
    for (int c = 0; c < 4; ++c)
#pragma unroll
        for (int k = 0; k < 9; ++k) wreg[c][k] = sW[(c0 + c) * 9 + k];
    float4 bias = *(const float4*)(b0  + c0);
    float4 gv   = *(const float4*)(g0  + c0);
    float4 bev  = *(const float4*)(be0 + c0);

    int node = blockIdx.x * 8 + wid;
    if (node >= NN) return;
    float t = (lane < 9) ? x[(size_t)node * 9 + lane] : 0.f;
    float xv[9];
#pragma unroll
    for (int k = 0; k < 9; ++k) xv[k] = __shfl_sync(0xffffffffu, t, k);
    float v[4] = { bias.x, bias.y, bias.z, bias.w };
#pragma unroll
    for (int c = 0; c < 4; ++c)
#pragma unroll
        for (int k = 0; k < 9; ++k) v[c] = fmaf(xv[k], wreg[c][k], v[c]);
    float s  = v[0] + v[1] + v[2] + v[3];
    float s2 = v[0]*v[0] + v[1]*v[1] + v[2]*v[2] + v[3]*v[3];
#pragma unroll
    for (int off = 16; off; off >>= 1) {
        s  += __shfl_xor_sync(0xffffffffu, s, off);
        s2 += __shfl_xor_sync(0xffffffffu, s2, off);
    }
    float m   = s * (1.f / HH);
    float var = s2 * (1.f / HH) - m * m;
    float rs  = rsqrtf(var + LN_EPS);
    float4 o;
    o.x = fmaxf((v[0] - m) * rs * gv.x + bev.x, 0.f);
    o.y = fmaxf((v[1] - m) * rs * gv.y + bev.y, 0.f);
    o.z = fmaxf((v[2] - m) * rs * gv.z + bev.z, 0.f);
    o.w = fmaxf((v[3] - m) * rs * gv.w + bev.w, 0.f);
    *(float4*)(d_bufA + (size_t)node * HH + c0) = o;
}

// ---------------- gather aggregation: agg[i] = inv[i] * sum_j h[csr[j]] ------
__global__ __launch_bounds__(256) void k_gather(const float* __restrict__ h) {
    int node = (blockIdx.x * 256 + threadIdx.x) >> 5;
    int lane = threadIdx.x & 31;
    if (node >= NN) return;
    int e   = d_rowptr[node];
    int end = d_rowptr[node + 1];
    float ax = 0.f, ay = 0.f, az = 0.f, aw = 0.f;
    for (; e + 4 <= end; e += 4) {
        int s0 = d_csrc[e], s1 = d_csrc[e + 1], s2 = d_csrc[e + 2], s3 = d_csrc[e + 3];
        float4 v0 = *(const float4*)(h + (size_t)s0 * HH + lane * 4);
        float4 v1 = *(const float4*)(h + (size_t)s1 * HH + lane * 4);
        float4 v2 = *(const float4*)(h + (size_t)s2 * HH + lane * 4);
        float4 v3 = *(const float4*)(h + (size_t)s3 * HH + lane * 4);
        ax += (v0.x + v1.x) + (v2.x + v3.x);
        ay += (v0.y + v1.y) + (v2.y + v3.y);
        az += (v0.z + v1.z) + (v2.z + v3.z);
        aw += (v0.w + v1.w) + (v2.w + v3.w);
    }
    for (; e < end; ++e) {
        int s = d_csrc[e];
        float4 v = *(const float4*)(h + (size_t)s * HH + lane * 4);
        ax += v.x; ay += v.y; az += v.z; aw += v.w;
    }
    float sc = d_inv[node];
    float4 o = make_float4(ax * sc, ay * sc, az * sc, aw * sc);
    *(float4*)(d_agg + (size_t)node * HH + lane * 4) = o;
}

// ---------------- fused dual-GEMM + bias + LN + ReLU, FFMA2 inner loop -------
// out[i,:] = relu(LN( agg[i] @ Wl^T + bl + h[i] @ Wr^T ))
// BM=128, BN=128, BK=32; 256 threads; warp = 16 rows (8 row-pairs), lane = 4 cols.
__global__ __launch_bounds__(256) void k_gemm(
    const float* __restrict__ h,
    const float* __restrict__ Wl, const float* __restrict__ bl,
    const float* __restrict__ Wr,
    const float* __restrict__ gamma, const float* __restrict__ beta,
    float* __restrict__ out)
{
    __shared__ __align__(16) float Ast[32][132];   // transposed A tile: [k][row]
    __shared__ __align__(16) float Bs [32][132];   // transposed W tile: [k][outcol]
    int tid  = threadIdx.x;
    int wid  = tid >> 5;             // warp -> rows wid*16 .. +15
    int lane = tid & 31;             // lane -> cols lane*4 .. +3
    int row0 = blockIdx.x * 128;
    unsigned long long acc[8][4];    // [row-pair][col], packed {row 2p, row 2p+1}
#pragma unroll
    for (int p = 0; p < 8; ++p)
        acc[p][0] = acc[p][1] = acc[p][2] = acc[p][3] = 0ULL;

#pragma unroll 1
    for (int mat = 0; mat < 2; ++mat) {
        const float* A = mat ? h  : d_agg;
        const float* W = mat ? Wr : Wl;
#pragma unroll 1
        for (int k0 = 0; k0 < HH; k0 += 32) {
            // A tile: 128x32 floats = 1024 float4, 4/thread, coalesced rows
#pragma unroll
            for (int i = 0; i < 4; ++i) {
                int idx = tid + i * 256;
                int r = idx >> 3, c = idx & 7;
                int gr = row0 + r;
                float4 v = make_float4(0.f, 0.f, 0.f, 0.f);
                if (gr < NN) v = *(const float4*)(A + (size_t)gr * HH + k0 + c * 4);
                Ast[c * 4 + 0][r] = v.x; Ast[c * 4 + 1][r] = v.y;
                Ast[c * 4 + 2][r] = v.z; Ast[c * 4 + 3][r] = v.w;
            }
            // B tile: 128 outcols x 32 k = 1024 float4, 4/thread
#pragma unroll
            for (int i = 0; i < 4; ++i) {
                int idx = tid + i * 256;
                int j = idx >> 3, c = idx & 7;
                float4 v = *(const float4*)(W + (size_t)j * HH + k0 + c * 4);
                Bs[c * 4 + 0][j] = v.x; Bs[c * 4 + 1][j] = v.y;
                Bs[c * 4 + 2][j] = v.z; Bs[c * 4 + 3][j] = v.w;
            }
            __syncthreads();
#pragma unroll 8
            for (int k = 0; k < 32; ++k) {
                float4 b = *(const float4*)&Bs[k][lane * 4];  // LDS.128, conflict-free
                unsigned long long bd[4];
                unsigned int bx = __float_as_uint(b.x), by = __float_as_uint(b.y);
                unsigned int bz = __float_as_uint(b.z), bw = __float_as_uint(b.w);
                PACK2(bd[0], bx, bx); PACK2(bd[1], by, by);
                PACK2(bd[2], bz, bz); PACK2(bd[3], bw, bw);
#pragma unroll
                for (int p = 0; p < 8; ++p) {
                    unsigned long long a2 =
                        *(const unsigned long long*)&Ast[k][wid * 16 + 2 * p];  // LDS.64 bcast
                    FMA2(acc[p][0], a2, bd[0], acc[p][0]);
                    FMA2(acc[p][1], a2, bd[1], acc[p][1]);
                    FMA2(acc[p][2], a2, bd[2], acc[p][2]);
                    FMA2(acc[p][3], a2, bd[3], acc[p][3]);
                }
            }
            __syncthreads();
        }
    }

    // bias + LayerNorm + ReLU directly from registers
    float4 blv = *(const float4*)(bl    + lane * 4);
    float4 gv  = *(const float4*)(gamma + lane * 4);
    float4 bev = *(const float4*)(beta  + lane * 4);
#pragma unroll
    for (int p = 0; p < 8; ++p) {
        float rowv[2][4];
#pragma unroll
        for (int c = 0; c < 4; ++c) {
            unsigned int lo, hi;
            UNPK2(lo, hi, acc[p][c]);
            rowv[0][c] = __uint_as_float(lo);
            rowv[1][c] = __uint_as_float(hi);
        }
#pragma unroll
        for (int half = 0; half < 2; ++half) {
            int gr = row0 + wid * 16 + 2 * p + half;
            float4 v = make_float4(rowv[half][0] + blv.x, rowv[half][1] + blv.y,
                                   rowv[half][2] + blv.z, rowv[half][3] + blv.w);
            float s  = v.x + v.y + v.z + v.w;
            float s2 = v.x * v.x + v.y * v.y + v.z * v.z + v.w * v.w;
#pragma unroll
            for (int off = 16; off; off >>= 1) {
                s  += __shfl_xor_sync(0xffffffffu, s, off);
                s2 += __shfl_xor_sync(0xffffffffu, s2, off);
            }
            float m   = s * (1.f / HH);
            float var = s2 * (1.f / HH) - m * m;
            float rs  = rsqrtf(var + LN_EPS);
            float4 o;
            o.x = fmaxf((v.x - m) * rs * gv.x + bev.x, 0.f);
            o.y = fmaxf((v.y - m) * rs * gv.y + bev.y, 0.f);
            o.z = fmaxf((v.z - m) * rs * gv.z + bev.z, 0.f);
            o.w = fmaxf((v.w - m) * rs * gv.w + bev.w, 0.f);
            if (gr < NN) *(float4*)(out + (size_t)gr * HH + lane * 4) = o;
        }
    }
}

// ---------------- pooling ----------------
__global__ __launch_bounds__(256) void k_pool(
    const float* __restrict__ ne, const int* __restrict__ batch,
    float* __restrict__ out_graph)
{
    int gw = (blockIdx.x * 256 + threadIdx.x) >> 5;
    int lane = threadIdx.x & 31;
    if (gw >= NN) return;
    int b = batch[gw];
    float4 v = *(const float4*)(ne + (size_t)gw * HH + lane * 4);
    float* s = d_gsum + b * HH + lane * 4;
    atomicAdd(s + 0, v.x); atomicAdd(s + 1, v.y);
    atomicAdd(s + 2, v.z); atomicAdd(s + 3, v.w);
    int* mx = (int*)(out_graph + b * (2 * HH) + HH + lane * 4);
    atomicMax(mx + 0, __float_as_int(v.x));   // relu'd (>=0): int order == float order
    atomicMax(mx + 1, __float_as_int(v.y));
    atomicMax(mx + 2, __float_as_int(v.z));
    atomicMax(mx + 3, __float_as_int(v.w));
    if (lane == 0) atomicAdd(&d_gcnt[b], 1);
}

__global__ void k_fin(float* __restrict__ out_graph) {
    int i = blockIdx.x * blockDim.x + threadIdx.x;
    if (i >= BB * HH) return;
    int b = i >> 7, j = i & 127;
    float c = (float)max(d_gcnt[b], 1);
    out_graph[b * (2 * HH) + j] = d_gsum[i] / c;
}

// ---------------- launch ----------------
extern "C" void kernel_launch(void* const* d_in, const int* in_sizes, int n_in,
                              void* d_out, int out_size)
{
    const float* x     = (const float*)d_in[0];
    const int*   ei    = (const int*)  d_in[1];
    const int*   batch = (const int*)  d_in[2];
    const float* W0  = (const float*)d_in[3];
    const float* b0  = (const float*)d_in[4];
    const float* g0  = (const float*)d_in[5];
    const float* be0 = (const float*)d_in[6];
    const float* Wl[3] = { (const float*)d_in[7],  (const float*)d_in[12], (const float*)d_in[17] };
    const float* bl[3] = { (const float*)d_in[8],  (const float*)d_in[13], (const float*)d_in[18] };
    const float* Wr[3] = { (const float*)d_in[9],  (const float*)d_in[14], (const float*)d_in[19] };
    const float* gg[3] = { (const float*)d_in[10], (const float*)d_in[15], (const float*)d_in[20] };
    const float* bb[3] = { (const float*)d_in[11], (const float*)d_in[16], (const float*)d_in[21] };

    float* out       = (float*)d_out;
    float* out_graph = out + (size_t)NN * HH;

    void *pA = nullptr, *pB = nullptr;
    cudaGetSymbolAddress(&pA, d_bufA);
    cudaGetSymbolAddress(&pB, d_bufB);
    float* bufA = (float*)pA;
    float* bufB = (float*)pB;

    k_init<<<(NN + 255) / 256, 256>>>(out_graph);
    k_deg <<<(EE + 255) / 256, 256>>>(ei);
    k_inv <<<(NN + 255) / 256, 256>>>();
    k_scan1<<<SCAN_B, 256>>>();
    k_scan2<<<1, 512>>>();
    k_scan3<<<SCAN_B, 256>>>();
    k_csr <<<(EE + 255) / 256, 256>>>(ei);
    k_embed<<<(NN + 7) / 8, 256>>>(x, W0, b0, g0, be0);

    const float* hin = bufA;
    for (int l = 0; l < 3; ++l) {
        k_gather<<<(NN + 7) / 8, 256>>>(hin);
        float* ho = (l == 2) ? out : ((l == 0) ? bufB : bufA);
        k_gemm<<<(NN + 127) / 128, 256>>>(hin, Wl[l], bl[l], Wr[l], gg[l], bb[l], ho);
        hin = ho;
    }

    k_pool<<<NN / 8, 256>>>(out, batch, out_graph);
    k_fin <<<(BB * HH + 255) / 256, 256>>>(out_graph);
}